// round 3
// baseline (speedup 1.0000x reference)
#include <cuda_runtime.h>
#include <math.h>

// Problem constants
#define T_TOK 4096      // B*S = 2*2048
#define HID   4096
#define BOT   64
#define RDIM  48
#define NSLOT 1024
#define TOPK  8
#define VB    256
#define HID4  1024      // HID/4

// ---------------- scratch (static device memory; no allocations) ----------------
__device__ float g_rkT[RDIM * NSLOT];          // rk transposed [48][1024]
__device__ float g_AV2part[4 * NSLOT * VB];    // k-split partials for AV2
__device__ float g_AV2[NSLOT * VB];            // aux_values @ Wvd^T  [1024,256]
__device__ float g_qpart[8 * T_TOK * BOT];     // k-split partials for query
__device__ float g_query[T_TOK * BOT];         // h @ Wq^T [4096,64]
__device__ float g_logvar[T_TOK];
__device__ float g_mean[1];
__device__ float g_lpart[T_TOK * 8];           // per-nblock partial of gelu(z)·Wu2
__device__ float g_gate[T_TOK];
__device__ float g_tmp[T_TOK * VB];            // Σ w_k AV2[idx_k]  [4096,256]

__device__ __forceinline__ float gelu_tanh(float x) {
    float x3 = x * x * x;
    return 0.5f * x * (1.0f + tanhf(0.7978845608028654f * (x + 0.044715f * x3)));
}

// ---------------- tiny: rk^T = (aux_keys @ Wr^T)^T ----------------
__global__ void rk_kernel(const float* __restrict__ aux_keys,
                          const float* __restrict__ Wr) {
    int n = blockIdx.x * blockDim.x + threadIdx.x;
    if (n >= NSLOT) return;
    float ak[BOT];
#pragma unroll
    for (int d = 0; d < BOT; d++) ak[d] = aux_keys[n * BOT + d];
    for (int r = 0; r < RDIM; r++) {
        float s = 0.f;
#pragma unroll
        for (int d = 0; d < BOT; d++) s += ak[d] * Wr[r * BOT + d];
        g_rkT[r * NSLOT + n] = s;
    }
}

// ---------------- small k-split GEMM: C = A[M,K] * B[N,K]^T ----------------
// 64x64 tile, BK=16, 256 threads, 4x4 per thread. dst: 0 -> g_qpart, 1 -> g_AV2part
__global__ __launch_bounds__(256) void small_gemm_kernel(
    const float* __restrict__ A, const float* __restrict__ B,
    int N, int K, int kchunk, int dst) {
    __shared__ float As[16][64];
    __shared__ float Bs[16][64];
    int tid = threadIdx.x;
    int tx = tid & 15, ty = tid >> 4;
    int m0 = blockIdx.x * 64, n0 = blockIdx.y * 64;
    int k0 = blockIdx.z * kchunk;
    int lr = tid >> 2, lk = (tid & 3) * 4;
    const float* Ap = A + (size_t)(m0 + lr) * K + k0 + lk;
    const float* Bp = B + (size_t)(n0 + lr) * K + k0 + lk;
    float acc[4][4];
#pragma unroll
    for (int i = 0; i < 4; i++)
#pragma unroll
        for (int j = 0; j < 4; j++) acc[i][j] = 0.f;

    for (int kt = 0; kt < kchunk; kt += 16) {
        float4 a = *(const float4*)(Ap + kt);
        float4 b = *(const float4*)(Bp + kt);
        __syncthreads();
        As[lk + 0][lr] = a.x; As[lk + 1][lr] = a.y; As[lk + 2][lr] = a.z; As[lk + 3][lr] = a.w;
        Bs[lk + 0][lr] = b.x; Bs[lk + 1][lr] = b.y; Bs[lk + 2][lr] = b.z; Bs[lk + 3][lr] = b.w;
        __syncthreads();
#pragma unroll
        for (int k = 0; k < 16; k++) {
            float4 av = *(const float4*)&As[k][ty * 4];
            float4 bv = *(const float4*)&Bs[k][tx * 4];
            float avv[4] = {av.x, av.y, av.z, av.w};
            float bvv[4] = {bv.x, bv.y, bv.z, bv.w};
#pragma unroll
            for (int i = 0; i < 4; i++)
#pragma unroll
                for (int j = 0; j < 4; j++) acc[i][j] += avv[i] * bvv[j];
        }
    }
    int M = gridDim.x * 64;
    float* Cz = (dst ? g_AV2part : g_qpart) + (size_t)blockIdx.z * M * N;
#pragma unroll
    for (int i = 0; i < 4; i++) {
        int row = m0 + ty * 4 + i;
        *(float4*)&Cz[(size_t)row * N + n0 + tx * 4] =
            make_float4(acc[i][0], acc[i][1], acc[i][2], acc[i][3]);
    }
}

// which: 0 -> sum g_qpart into g_query, 1 -> sum g_AV2part into g_AV2
__global__ void reduce_parts_kernel(int which, int count, int z) {
    int i = blockIdx.x * blockDim.x + threadIdx.x;
    if (i >= count) return;
    const float* part = which ? g_AV2part : g_qpart;
    float s = 0.f;
    for (int p = 0; p < z; p++) s += part[(size_t)p * count + i];
    (which ? g_AV2 : g_query)[i] = s;
}

// ---------------- per-token variance ----------------
__global__ void var_kernel(const float* __restrict__ H) {
    int t = blockIdx.x * 4 + (threadIdx.x >> 5);
    int lane = threadIdx.x & 31;
    const float4* h4 = (const float4*)(H + (size_t)t * HID);
    float s = 0.f, sq = 0.f;
    for (int i = lane; i < HID / 4; i += 32) {
        float4 v = h4[i];
        s += v.x + v.y + v.z + v.w;
        sq += v.x * v.x + v.y * v.y + v.z * v.z + v.w * v.w;
    }
#pragma unroll
    for (int o = 16; o; o >>= 1) {
        s += __shfl_xor_sync(0xffffffffu, s, o);
        sq += __shfl_xor_sync(0xffffffffu, sq, o);
    }
    if (lane == 0) {
        float mean = s * (1.0f / HID);
        float var = sq * (1.0f / HID) - mean * mean;
        g_logvar[t] = log1pf(var);
    }
}

__global__ void mean_kernel() {
    __shared__ float sm[1024];
    int tid = threadIdx.x;
    float s = g_logvar[tid] + g_logvar[tid + 1024] + g_logvar[tid + 2048] + g_logvar[tid + 3072];
    sm[tid] = s;
    __syncthreads();
    for (int o = 512; o; o >>= 1) {
        if (tid < o) sm[tid] += sm[tid + o];
        __syncthreads();
    }
    if (tid == 0) g_mean[0] = sm[0] * (1.0f / T_TOK);
}

// ---------------- big GEMM #1: z = h @ Wu1^T, epilogue gelu(z+bu1)·Wu2 partial reduce --------
// 128x128 tile, BK=8, 256 threads, 8x8 per thread (2x4 split fragments)
__global__ __launch_bounds__(256) void gemm_g2_kernel(
    const float* __restrict__ A,   // h   [4096,4096]
    const float* __restrict__ B,   // Wu1 [1024,4096]
    const float* __restrict__ bu1, // [1024]
    const float* __restrict__ Wu2) // [1024]
{
    const int K = HID;
    __shared__ float As[8][128];
    __shared__ float Bs[8][128];
    __shared__ float red[128][17];
    int tid = threadIdx.x;
    int tx = tid & 15, ty = tid >> 4;
    int m0 = blockIdx.x * 128, n0 = blockIdx.y * 128;
    int lr = tid >> 1, lk = (tid & 1) * 4;
    const float* Ap = A + (size_t)(m0 + lr) * K + lk;
    const float* Bp = B + (size_t)(n0 + lr) * K + lk;
    float4 pa = *(const float4*)Ap;
    float4 pb = *(const float4*)Bp;
    float acc[8][8];
#pragma unroll
    for (int i = 0; i < 8; i++)
#pragma unroll
        for (int j = 0; j < 8; j++) acc[i][j] = 0.f;

    for (int kt = 0; kt < K; kt += 8) {
        __syncthreads();
        As[lk + 0][lr] = pa.x; As[lk + 1][lr] = pa.y; As[lk + 2][lr] = pa.z; As[lk + 3][lr] = pa.w;
        Bs[lk + 0][lr] = pb.x; Bs[lk + 1][lr] = pb.y; Bs[lk + 2][lr] = pb.z; Bs[lk + 3][lr] = pb.w;
        __syncthreads();
        if (kt + 8 < K) {
            pa = *(const float4*)(Ap + kt + 8);
            pb = *(const float4*)(Bp + kt + 8);
        }
#pragma unroll
        for (int k = 0; k < 8; k++) {
            float4 a0 = *(const float4*)&As[k][ty * 4];
            float4 a1 = *(const float4*)&As[k][64 + ty * 4];
            float4 b0 = *(const float4*)&Bs[k][tx * 4];
            float4 b1 = *(const float4*)&Bs[k][64 + tx * 4];
            float av[8] = {a0.x, a0.y, a0.z, a0.w, a1.x, a1.y, a1.z, a1.w};
            float bv[8] = {b0.x, b0.y, b0.z, b0.w, b1.x, b1.y, b1.z, b1.w};
#pragma unroll
            for (int i = 0; i < 8; i++)
#pragma unroll
                for (int j = 0; j < 8; j++) acc[i][j] += av[i] * bv[j];
        }
    }
    // epilogue: gelu + weighted reduce over this block's 128 N-columns
    float bu[8], w2[8];
#pragma unroll
    for (int j = 0; j < 4; j++) {
        int c0 = n0 + tx * 4 + j;
        int c1 = n0 + 64 + tx * 4 + j;
        bu[j] = bu1[c0]; w2[j] = Wu2[c0];
        bu[4 + j] = bu1[c1]; w2[4 + j] = Wu2[c1];
    }
#pragma unroll
    for (int i = 0; i < 8; i++) {
        float s = 0.f;
#pragma unroll
        for (int j = 0; j < 8; j++) {
            float z = acc[i][j] + bu[j];
            s += gelu_tanh(z) * w2[j];
        }
        int row = (i < 4) ? (ty * 4 + i) : (64 + ty * 4 + i - 4);
        red[row][tx] = s;
    }
    __syncthreads();
    if (tid < 128) {
        float s = 0.f;
#pragma unroll
        for (int x = 0; x < 16; x++) s += red[tid][x];
        g_lpart[(size_t)(m0 + tid) * 8 + blockIdx.y] = s;
    }
}

// ---------------- gate ----------------
__global__ void gate_kernel(const float* __restrict__ bu2,
                            const float* __restrict__ gw1,
                            const float* __restrict__ gb) {
    int t = blockIdx.x * blockDim.x + threadIdx.x;
    if (t >= T_TOK) return;
    float learned = bu2[0];
#pragma unroll
    for (int p = 0; p < 8; p++) learned += g_lpart[t * 8 + p];
    float sl = 1.0f / (1.0f + expf(-learned));
    float nv = g_logvar[t] / (g_mean[0] + 1e-6f);
    float u = nv * 0.5f + sl * 2.5f;
    u = fminf(fmaxf(u, 0.0f), 5.0f);
    float un = fminf(fmaxf((u - 0.5f) * (1.0f / 1.5f), 0.0f), 1.0f);
    float g = 1.0f / (1.0f + expf(-(gw1[0] * un + gb[0])));
    if (g < 0.05f) g = 0.0f;
    g_gate[t] = g;
}

// ---------------- router: scores, top-8, attn softmax, tmp = Σ w_k AV2[idx_k] ------
// 4 tokens per block, 256 threads
__global__ __launch_bounds__(256) void router_kernel(
    const float* __restrict__ Wr,       // [48,64]
    const float* __restrict__ log_rel,  // [1024]
    const float* __restrict__ aux_keys) // [1024,64]
{
    __shared__ float q[4][BOT];
    __shared__ float rq[4][RDIM];
    __shared__ float sc[4][NSLOT];
    __shared__ float redv[256];
    __shared__ int redi[256];
    __shared__ int sidx[4][TOPK];
    __shared__ float sw[4][TOPK];
    int tid = threadIdx.x;
    int tok0 = blockIdx.x * 4;

    q[tid >> 6][tid & 63] = g_query[(size_t)(tok0 + (tid >> 6)) * BOT + (tid & 63)];
    __syncthreads();
    if (tid < 4 * RDIM) {
        int tk = tid / RDIM, r = tid % RDIM;
        float s = 0.f;
#pragma unroll
        for (int d = 0; d < BOT; d++) s += q[tk][d] * Wr[r * BOT + d];
        rq[tk][r] = s;
    }
    __syncthreads();
    const float scale = 0.14433756729740643f; // 1/sqrt(48)
    for (int n = tid; n < NSLOT; n += 256) {
        float s0 = 0.f, s1 = 0.f, s2 = 0.f, s3 = 0.f;
#pragma unroll 8
        for (int r = 0; r < RDIM; r++) {
            float v = g_rkT[r * NSLOT + n];
            s0 += rq[0][r] * v; s1 += rq[1][r] * v;
            s2 += rq[2][r] * v; s3 += rq[3][r] * v;
        }
        float lr = log_rel[n];
        sc[0][n] = s0 * scale + lr; sc[1][n] = s1 * scale + lr;
        sc[2][n] = s2 * scale + lr; sc[3][n] = s3 * scale + lr;
    }
    __syncthreads();
    // top-8 per token (argmax x8, lowest-index tiebreak like lax.top_k)
    for (int tk = 0; tk < 4; tk++) {
        for (int it = 0; it < TOPK; it++) {
            float best = -3.0e38f; int bi = 1 << 30;
            for (int n = tid; n < NSLOT; n += 256) {
                float v = sc[tk][n];
                if (v > best || (v == best && n < bi)) { best = v; bi = n; }
            }
            redv[tid] = best; redi[tid] = bi;
            __syncthreads();
            for (int o = 128; o; o >>= 1) {
                if (tid < o) {
                    float v = redv[tid + o]; int i2 = redi[tid + o];
                    if (v > redv[tid] || (v == redv[tid] && i2 < redi[tid])) {
                        redv[tid] = v; redi[tid] = i2;
                    }
                }
                __syncthreads();
            }
            if (tid == 0) { sidx[tk][it] = redi[0]; sc[tk][redi[0]] = -3.0e38f; }
            __syncthreads();
        }
    }
    // attention logits: warp w handles slot w for each token
    int w = tid >> 5, lane = tid & 31;
    for (int tk = 0; tk < 4; tk++) {
        int i = sidx[tk][w];
        float s = q[tk][lane] * aux_keys[i * BOT + lane] +
                  q[tk][lane + 32] * aux_keys[i * BOT + lane + 32];
#pragma unroll
        for (int o = 16; o; o >>= 1) s += __shfl_xor_sync(0xffffffffu, s, o);
        if (lane == 0) sw[tk][w] = s * 0.125f + log_rel[i];
    }
    __syncthreads();
    if (tid < 4) {
        int tk = tid;
        float m = -3.0e38f;
#pragma unroll
        for (int k2 = 0; k2 < TOPK; k2++) m = fmaxf(m, sw[tk][k2]);
        float e[TOPK], ssum = 0.f;
#pragma unroll
        for (int k2 = 0; k2 < TOPK; k2++) { e[k2] = expf(sw[tk][k2] - m); ssum += e[k2]; }
        float inv = 1.0f / ssum;
#pragma unroll
        for (int k2 = 0; k2 < TOPK; k2++) sw[tk][k2] = e[k2] * inv;
    }
    __syncthreads();
    for (int tk = 0; tk < 4; tk++) {
        float a = 0.f;
#pragma unroll
        for (int k2 = 0; k2 < TOPK; k2++)
            a += sw[tk][k2] * g_AV2[(size_t)sidx[tk][k2] * VB + tid];
        g_tmp[(size_t)(tok0 + tk) * VB + tid] = a;
    }
}

// ---------------- big GEMM #2: out = h + gate * (tmp @ Wvu^T) ----------------
__global__ __launch_bounds__(256) void gemm_out_kernel(
    const float* __restrict__ B,   // Wvu [4096,256]
    const float* __restrict__ H,   // hidden [4096,4096]
    float* __restrict__ out) {
    const int K = VB;
    __shared__ float As[8][128];
    __shared__ float Bs[8][128];
    int tid = threadIdx.x;
    int tx = tid & 15, ty = tid >> 4;
    int m0 = blockIdx.x * 128, n0 = blockIdx.y * 128;
    int lr = tid >> 1, lk = (tid & 1) * 4;
    const float* Ap = g_tmp + (size_t)(m0 + lr) * K + lk;
    const float* Bp = B + (size_t)(n0 + lr) * K + lk;
    float4 pa = *(const float4*)Ap;
    float4 pb = *(const float4*)Bp;
    float acc[8][8];
#pragma unroll
    for (int i = 0; i < 8; i++)
#pragma unroll
        for (int j = 0; j < 8; j++) acc[i][j] = 0.f;

    for (int kt = 0; kt < K; kt += 8) {
        __syncthreads();
        As[lk + 0][lr] = pa.x; As[lk + 1][lr] = pa.y; As[lk + 2][lr] = pa.z; As[lk + 3][lr] = pa.w;
        Bs[lk + 0][lr] = pb.x; Bs[lk + 1][lr] = pb.y; Bs[lk + 2][lr] = pb.z; Bs[lk + 3][lr] = pb.w;
        __syncthreads();
        if (kt + 8 < K) {
            pa = *(const float4*)(Ap + kt + 8);
            pb = *(const float4*)(Bp + kt + 8);
        }
#pragma unroll
        for (int k = 0; k < 8; k++) {
            float4 a0 = *(const float4*)&As[k][ty * 4];
            float4 a1 = *(const float4*)&As[k][64 + ty * 4];
            float4 b0 = *(const float4*)&Bs[k][tx * 4];
            float4 b1 = *(const float4*)&Bs[k][64 + tx * 4];
            float av[8] = {a0.x, a0.y, a0.z, a0.w, a1.x, a1.y, a1.z, a1.w};
            float bv[8] = {b0.x, b0.y, b0.z, b0.w, b1.x, b1.y, b1.z, b1.w};
#pragma unroll
            for (int i = 0; i < 8; i++)
#pragma unroll
                for (int j = 0; j < 8; j++) acc[i][j] += av[i] * bv[j];
        }
    }
#pragma unroll
    for (int i = 0; i < 8; i++) {
        int row = m0 + ((i < 4) ? (ty * 4 + i) : (64 + ty * 4 + i - 4));
        float g = g_gate[row];
#pragma unroll
        for (int half = 0; half < 2; half++) {
            int c = n0 + half * 64 + tx * 4;
            float4 hv = *(const float4*)&H[(size_t)row * HID + c];
            float4 o;
            o.x = hv.x + g * acc[i][half * 4 + 0];
            o.y = hv.y + g * acc[i][half * 4 + 1];
            o.z = hv.z + g * acc[i][half * 4 + 2];
            o.w = hv.w + g * acc[i][half * 4 + 3];
            *(float4*)&out[(size_t)row * HID + c] = o;
        }
    }
}

// ---------------- launch ----------------
extern "C" void kernel_launch(void* const* d_in, const int* in_sizes, int n_in,
                              void* d_out, int out_size) {
    const float* H        = (const float*)d_in[0];
    const float* Wq       = (const float*)d_in[1];
    const float* Wr       = (const float*)d_in[2];
    const float* aux_keys = (const float*)d_in[3];
    const float* aux_vals = (const float*)d_in[4];
    const float* Wvd      = (const float*)d_in[5];
    const float* Wvu      = (const float*)d_in[6];
    const float* Wu1      = (const float*)d_in[7];
    const float* bu1      = (const float*)d_in[8];
    const float* Wu2      = (const float*)d_in[9];
    const float* bu2      = (const float*)d_in[10];
    const float* gate_w1  = (const float*)d_in[11];
    const float* gate_b   = (const float*)d_in[12];
    const float* log_rel  = (const float*)d_in[13];
    float* out = (float*)d_out;

    // rk^T
    rk_kernel<<<4, 256>>>(aux_keys, Wr);
    // AV2 = aux_values @ Wvd^T  (M=1024,N=256,K=4096, ksplit 4)
    small_gemm_kernel<<<dim3(16, 4, 4), 256>>>(aux_vals, Wvd, VB, HID, 1024, 1);
    reduce_parts_kernel<<<(NSLOT * VB + 255) / 256, 256>>>(1, NSLOT * VB, 4);
    // query = h @ Wq^T  (M=4096,N=64,K=4096, ksplit 8)
    small_gemm_kernel<<<dim3(64, 1, 8), 256>>>(H, Wq, BOT, HID, 512, 0);
    reduce_parts_kernel<<<(T_TOK * BOT + 255) / 256, 256>>>(0, T_TOK * BOT, 8);
    // variance + deterministic global mean
    var_kernel<<<T_TOK / 4, 128>>>(H);
    mean_kernel<<<1, 1024>>>();
    // big: learned partials
    gemm_g2_kernel<<<dim3(T_TOK / 128, HID4 / 128), 256>>>(H, Wu1, bu1, Wu2);
    gate_kernel<<<(T_TOK + 255) / 256, 256>>>(bu2, gate_w1, gate_b);
    // routing + slot attention + bottleneck-down (via AV2)
    router_kernel<<<T_TOK / 4, 256>>>(Wr, log_rel, aux_keys);
    // out = h + gate * (tmp @ Wvu^T)
    gemm_out_kernel<<<dim3(T_TOK / 128, HID / 128), 256>>>(Wvu, H, out);
}

// round 4
// speedup vs baseline: 2.0704x; 2.0704x over previous
#include <cuda_runtime.h>
#include <cuda_bf16.h>
#include <mma.h>
#include <math.h>

using namespace nvcuda;

// Problem constants
#define T_TOK 4096      // B*S
#define HID   4096
#define BOT   64
#define RDIM  48
#define NSLOT 1024
#define TOPK  8
#define VB    256
#define HID4  1024      // HID/4

typedef __nv_bfloat16 bf16;

// ---------------- scratch (static device memory; no allocations) ----------------
__device__ bf16  g_hb[(size_t)T_TOK * HID];      // bf16 copy of hidden_states
__device__ bf16  g_wu1b[HID4 * HID];
__device__ bf16  g_wqb[BOT * HID];
__device__ bf16  g_wvdb[VB * HID];
__device__ bf16  g_avb[NSLOT * HID];
__device__ bf16  g_wvub[HID * VB];
__device__ bf16  g_tmpb[T_TOK * VB];             // router output (bf16)
__device__ float g_zbuf[(size_t)T_TOK * HID4];   // h @ Wu1^T
__device__ float g_zbuf2[(size_t)T_TOK * HID];   // tmp @ Wvu^T
__device__ float g_rkT[RDIM * NSLOT];            // rk transposed [48][1024]
__device__ float g_qpart[8 * T_TOK * BOT];
__device__ float g_query[T_TOK * BOT];
__device__ float g_AV2part[4 * NSLOT * VB];
__device__ float g_AV2[NSLOT * VB];              // aux_values @ Wvd^T
__device__ float g_logvar[T_TOK];
__device__ float g_mean[1];
__device__ float g_gate[T_TOK];

__device__ __forceinline__ float gelu_tanh(float x) {
    float x3 = x * x * x;
    return 0.5f * x * (1.0f + tanhf(0.7978845608028654f * (x + 0.044715f * x3)));
}

// ---------------- prepass: h -> bf16, fused per-token variance ----------------
__global__ __launch_bounds__(256) void conv_h_var_kernel(const float* __restrict__ H) {
    int row = blockIdx.x;
    int tid = threadIdx.x;
    const float4* h4 = (const float4*)(H + (size_t)row * HID);
    __nv_bfloat162* dst = (__nv_bfloat162*)(g_hb + (size_t)row * HID);
    float s = 0.f, sq = 0.f;
    for (int i = tid; i < HID / 4; i += 256) {
        float4 v = h4[i];
        s  += v.x + v.y + v.z + v.w;
        sq += v.x * v.x + v.y * v.y + v.z * v.z + v.w * v.w;
        dst[i * 2]     = __float22bfloat162_rn(make_float2(v.x, v.y));
        dst[i * 2 + 1] = __float22bfloat162_rn(make_float2(v.z, v.w));
    }
    __shared__ float ss[8], sqs[8];
#pragma unroll
    for (int o = 16; o; o >>= 1) {
        s  += __shfl_xor_sync(0xffffffffu, s, o);
        sq += __shfl_xor_sync(0xffffffffu, sq, o);
    }
    int w = tid >> 5, lane = tid & 31;
    if (lane == 0) { ss[w] = s; sqs[w] = sq; }
    __syncthreads();
    if (tid == 0) {
        float S = 0.f, SQ = 0.f;
#pragma unroll
        for (int i = 0; i < 8; i++) { S += ss[i]; SQ += sqs[i]; }
        float mean = S * (1.0f / HID);
        float var = SQ * (1.0f / HID) - mean * mean;
        g_logvar[row] = log1pf(var);
    }
}

// ---------------- generic fp32 -> bf16 conversion (dst by selector) ----------------
__global__ void convert_kernel(const float* __restrict__ src, int count2, int sel) {
    bf16* dst = (sel == 0) ? g_wqb : (sel == 1) ? g_wvdb : (sel == 2) ? g_avb
              : (sel == 3) ? g_wu1b : g_wvub;
    int i = blockIdx.x * 256 + threadIdx.x;
    if (i < count2) {
        float2 v = ((const float2*)src)[i];
        ((__nv_bfloat162*)dst)[i] = __float22bfloat162_rn(v);
    }
}

__global__ void mean_kernel() {
    __shared__ float sm[1024];
    int tid = threadIdx.x;
    float s = g_logvar[tid] + g_logvar[tid + 1024] + g_logvar[tid + 2048] + g_logvar[tid + 3072];
    sm[tid] = s;
    __syncthreads();
    for (int o = 512; o; o >>= 1) {
        if (tid < o) sm[tid] += sm[tid + o];
        __syncthreads();
    }
    if (tid == 0) g_mean[0] = sm[0] * (1.0f / T_TOK);
}

// ---------------- tiny: rk^T = (aux_keys @ Wr^T)^T ----------------
__global__ void rk_kernel(const float* __restrict__ aux_keys,
                          const float* __restrict__ Wr) {
    int n = blockIdx.x * blockDim.x + threadIdx.x;
    if (n >= NSLOT) return;
    float ak[BOT];
#pragma unroll
    for (int d = 0; d < BOT; d++) ak[d] = aux_keys[n * BOT + d];
    for (int r = 0; r < RDIM; r++) {
        float s = 0.f;
#pragma unroll
        for (int d = 0; d < BOT; d++) s += ak[d] * Wr[r * BOT + d];
        g_rkT[r * NSLOT + n] = s;
    }
}

// ---------------- WMMA GEMM: C = A[M,K]bf16 @ B[N,K]bf16^T (k-split via blockIdx.z) ------
// Block tile 128 x (64*NF), BK=32, 8 warps (warp tile 64 x 16*NF).
// sel: 0 query (g_hb,g_wqb -> g_qpart)   1 AV2 (g_avb,g_wvdb -> g_AV2part)
//      2 g2    (g_hb,g_wu1b -> g_zbuf)   3 out (g_tmpb,g_wvub -> g_zbuf2)
template<int NF>
__global__ __launch_bounds__(256) void wmma_gemm_kernel(int sel, int K, int kchunk) {
    constexpr int BN = 64 * NF;
    constexpr int WN = 16 * NF;
    const bf16* A; const bf16* B; float* C;
    if (sel == 0)      { A = g_hb;   B = g_wqb;  C = g_qpart;   }
    else if (sel == 1) { A = g_avb;  B = g_wvdb; C = g_AV2part; }
    else if (sel == 2) { A = g_hb;   B = g_wu1b; C = g_zbuf;    }
    else               { A = g_tmpb; B = g_wvub; C = g_zbuf2;   }

    __shared__ bf16 As[128][40];
    __shared__ bf16 Bs[BN][40];
    int tid = threadIdx.x;
    int wid = tid >> 5;
    int warp_m = wid >> 2, warp_n = wid & 3;
    int m0 = blockIdx.x * 128, n0 = blockIdx.y * BN;
    int k0 = blockIdx.z * kchunk;
    int ldc = gridDim.y * BN;
    int M = gridDim.x * 128;
    float* Cz = C + (size_t)blockIdx.z * M * ldc;

    wmma::fragment<wmma::accumulator, 16, 16, 16, float> c[4][NF];
#pragma unroll
    for (int i = 0; i < 4; i++)
#pragma unroll
        for (int j = 0; j < NF; j++) wmma::fill_fragment(c[i][j], 0.f);

    for (int kt = 0; kt < kchunk; kt += 32) {
#pragma unroll
        for (int ch = tid; ch < 512; ch += 256) {
            int r = ch >> 2, cc = ch & 3;
            *(uint4*)&As[r][cc * 8] = *(const uint4*)(A + (size_t)(m0 + r) * K + k0 + kt + cc * 8);
        }
#pragma unroll
        for (int ch = tid; ch < BN * 4; ch += 256) {
            int r = ch >> 2, cc = ch & 3;
            *(uint4*)&Bs[r][cc * 8] = *(const uint4*)(B + (size_t)(n0 + r) * K + k0 + kt + cc * 8);
        }
        __syncthreads();
#pragma unroll
        for (int kk = 0; kk < 32; kk += 16) {
            wmma::fragment<wmma::matrix_a, 16, 16, 16, bf16, wmma::row_major> a[4];
            wmma::fragment<wmma::matrix_b, 16, 16, 16, bf16, wmma::col_major> b[NF];
#pragma unroll
            for (int i = 0; i < 4; i++)
                wmma::load_matrix_sync(a[i], &As[warp_m * 64 + i * 16][kk], 40);
#pragma unroll
            for (int j = 0; j < NF; j++)
                wmma::load_matrix_sync(b[j], &Bs[warp_n * WN + j * 16][kk], 40);
#pragma unroll
            for (int i = 0; i < 4; i++)
#pragma unroll
                for (int j = 0; j < NF; j++)
                    wmma::mma_sync(c[i][j], a[i], b[j], c[i][j]);
        }
        __syncthreads();
    }
#pragma unroll
    for (int i = 0; i < 4; i++)
#pragma unroll
        for (int j = 0; j < NF; j++)
            wmma::store_matrix_sync(
                &Cz[(size_t)(m0 + warp_m * 64 + i * 16) * ldc + n0 + warp_n * WN + j * 16],
                c[i][j], ldc, wmma::mem_row_major);
}

// which: 0 -> sum g_qpart into g_query, 1 -> sum g_AV2part into g_AV2
__global__ void reduce_parts_kernel(int which, int count, int z) {
    int i = blockIdx.x * blockDim.x + threadIdx.x;
    if (i >= count) return;
    const float* part = which ? g_AV2part : g_qpart;
    float s = 0.f;
    for (int p = 0; p < z; p++) s += part[(size_t)p * count + i];
    (which ? g_AV2 : g_query)[i] = s;
}

// ---------------- fused: learned = gelu(z+bu1)·Wu2, then gate ----------------
__global__ __launch_bounds__(256) void gate_from_z_kernel(
    const float* __restrict__ bu1, const float* __restrict__ Wu2,
    const float* __restrict__ bu2, const float* __restrict__ gw1,
    const float* __restrict__ gb) {
    int wid = threadIdx.x >> 5, lane = threadIdx.x & 31;
    int row = blockIdx.x * 8 + wid;
    const float4* z4 = (const float4*)(g_zbuf + (size_t)row * HID4);
    const float4* b4 = (const float4*)bu1;
    const float4* w4 = (const float4*)Wu2;
    float s = 0.f;
    for (int i = lane; i < HID4 / 4; i += 32) {
        float4 z = z4[i], b = b4[i], w = w4[i];
        s += gelu_tanh(z.x + b.x) * w.x + gelu_tanh(z.y + b.y) * w.y
           + gelu_tanh(z.z + b.z) * w.z + gelu_tanh(z.w + b.w) * w.w;
    }
#pragma unroll
    for (int o = 16; o; o >>= 1) s += __shfl_xor_sync(0xffffffffu, s, o);
    if (lane == 0) {
        float learned = s + bu2[0];
        float sl = 1.0f / (1.0f + expf(-learned));
        float nv = g_logvar[row] / (g_mean[0] + 1e-6f);
        float u = fminf(fmaxf(nv * 0.5f + sl * 2.5f, 0.0f), 5.0f);
        float un = fminf(fmaxf((u - 0.5f) * (1.0f / 1.5f), 0.0f), 1.0f);
        float g = 1.0f / (1.0f + expf(-(gw1[0] * un + gb[0])));
        if (g < 0.05f) g = 0.0f;
        g_gate[row] = g;
    }
}

// ---------------- router: scores, top-8, attn softmax, tmp = Σ w_k AV2[idx_k] ------
__global__ __launch_bounds__(256) void router_kernel(
    const float* __restrict__ Wr,       // [48,64]
    const float* __restrict__ log_rel,  // [1024]
    const float* __restrict__ aux_keys) // [1024,64]
{
    __shared__ float q[4][BOT];
    __shared__ float rq[4][RDIM];
    __shared__ float sc[4][NSLOT];
    __shared__ float redv[256];
    __shared__ int redi[256];
    __shared__ int sidx[4][TOPK];
    __shared__ float sw[4][TOPK];
    int tid = threadIdx.x;
    int tok0 = blockIdx.x * 4;

    q[tid >> 6][tid & 63] = g_query[(size_t)(tok0 + (tid >> 6)) * BOT + (tid & 63)];
    __syncthreads();
    if (tid < 4 * RDIM) {
        int tk = tid / RDIM, r = tid % RDIM;
        float s = 0.f;
#pragma unroll
        for (int d = 0; d < BOT; d++) s += q[tk][d] * Wr[r * BOT + d];
        rq[tk][r] = s;
    }
    __syncthreads();
    const float scale = 0.14433756729740643f; // 1/sqrt(48)
    for (int n = tid; n < NSLOT; n += 256) {
        float s0 = 0.f, s1 = 0.f, s2 = 0.f, s3 = 0.f;
#pragma unroll 8
        for (int r = 0; r < RDIM; r++) {
            float v = g_rkT[r * NSLOT + n];
            s0 += rq[0][r] * v; s1 += rq[1][r] * v;
            s2 += rq[2][r] * v; s3 += rq[3][r] * v;
        }
        float lr = log_rel[n];
        sc[0][n] = s0 * scale + lr; sc[1][n] = s1 * scale + lr;
        sc[2][n] = s2 * scale + lr; sc[3][n] = s3 * scale + lr;
    }
    __syncthreads();
    for (int tk = 0; tk < 4; tk++) {
        for (int it = 0; it < TOPK; it++) {
            float best = -3.0e38f; int bi = 1 << 30;
            for (int n = tid; n < NSLOT; n += 256) {
                float v = sc[tk][n];
                if (v > best || (v == best && n < bi)) { best = v; bi = n; }
            }
            redv[tid] = best; redi[tid] = bi;
            __syncthreads();
            for (int o = 128; o; o >>= 1) {
                if (tid < o) {
                    float v = redv[tid + o]; int i2 = redi[tid + o];
                    if (v > redv[tid] || (v == redv[tid] && i2 < redi[tid])) {
                        redv[tid] = v; redi[tid] = i2;
                    }
                }
                __syncthreads();
            }
            if (tid == 0) { sidx[tk][it] = redi[0]; sc[tk][redi[0]] = -3.0e38f; }
            __syncthreads();
        }
    }
    int w = tid >> 5, lane = tid & 31;
    for (int tk = 0; tk < 4; tk++) {
        int i = sidx[tk][w];
        float s = q[tk][lane] * aux_keys[i * BOT + lane] +
                  q[tk][lane + 32] * aux_keys[i * BOT + lane + 32];
#pragma unroll
        for (int o = 16; o; o >>= 1) s += __shfl_xor_sync(0xffffffffu, s, o);
        if (lane == 0) sw[tk][w] = s * 0.125f + log_rel[i];
    }
    __syncthreads();
    if (tid < 4) {
        int tk = tid;
        float m = -3.0e38f;
#pragma unroll
        for (int k2 = 0; k2 < TOPK; k2++) m = fmaxf(m, sw[tk][k2]);
        float e[TOPK], ssum = 0.f;
#pragma unroll
        for (int k2 = 0; k2 < TOPK; k2++) { e[k2] = expf(sw[tk][k2] - m); ssum += e[k2]; }
        float inv = 1.0f / ssum;
#pragma unroll
        for (int k2 = 0; k2 < TOPK; k2++) sw[tk][k2] = e[k2] * inv;
    }
    __syncthreads();
    for (int tk = 0; tk < 4; tk++) {
        float a = 0.f;
#pragma unroll
        for (int k2 = 0; k2 < TOPK; k2++)
            a += sw[tk][k2] * g_AV2[(size_t)sidx[tk][k2] * VB + tid];
        g_tmpb[(size_t)(tok0 + tk) * VB + tid] = __float2bfloat16(a);
    }
}

// ---------------- final: out = h + gate * zbuf2 ----------------
__global__ __launch_bounds__(256) void residual_kernel(const float* __restrict__ H,
                                                       float* __restrict__ out) {
    size_t i = (size_t)blockIdx.x * 256 + threadIdx.x;  // float4 index
    float4 h = ((const float4*)H)[i];
    float4 z = ((const float4*)g_zbuf2)[i];
    float g = g_gate[i >> 10];  // 1024 float4 per row
    ((float4*)out)[i] = make_float4(h.x + g * z.x, h.y + g * z.y,
                                    h.z + g * z.z, h.w + g * z.w);
}

// ---------------- launch ----------------
extern "C" void kernel_launch(void* const* d_in, const int* in_sizes, int n_in,
                              void* d_out, int out_size) {
    const float* H        = (const float*)d_in[0];
    const float* Wq       = (const float*)d_in[1];
    const float* Wr       = (const float*)d_in[2];
    const float* aux_keys = (const float*)d_in[3];
    const float* aux_vals = (const float*)d_in[4];
    const float* Wvd      = (const float*)d_in[5];
    const float* Wvu      = (const float*)d_in[6];
    const float* Wu1      = (const float*)d_in[7];
    const float* bu1      = (const float*)d_in[8];
    const float* Wu2      = (const float*)d_in[9];
    const float* bu2      = (const float*)d_in[10];
    const float* gate_w1  = (const float*)d_in[11];
    const float* gate_b   = (const float*)d_in[12];
    const float* log_rel  = (const float*)d_in[13];
    float* out = (float*)d_out;

    // prepass: h -> bf16 + per-token variance; weight conversions
    conv_h_var_kernel<<<T_TOK, 256>>>(H);
    mean_kernel<<<1, 1024>>>();
    convert_kernel<<<(BOT * HID / 2 + 255) / 256, 256>>>(Wq, BOT * HID / 2, 0);
    convert_kernel<<<(VB * HID / 2 + 255) / 256, 256>>>(Wvd, VB * HID / 2, 1);
    convert_kernel<<<(NSLOT * HID / 2 + 255) / 256, 256>>>(aux_vals, NSLOT * HID / 2, 2);
    convert_kernel<<<(HID4 * HID / 2 + 255) / 256, 256>>>(Wu1, HID4 * HID / 2, 3);
    convert_kernel<<<(HID * VB / 2 + 255) / 256, 256>>>(Wvu, HID * VB / 2, 4);
    rk_kernel<<<4, 256>>>(aux_keys, Wr);

    // query = h @ Wq^T  (k-split 8)
    wmma_gemm_kernel<1><<<dim3(32, 1, 8), 256>>>(0, HID, 512);
    reduce_parts_kernel<<<(T_TOK * BOT + 255) / 256, 256>>>(0, T_TOK * BOT, 8);
    // AV2 = aux_values @ Wvd^T  (k-split 4)
    wmma_gemm_kernel<2><<<dim3(8, 2, 4), 256>>>(1, HID, 1024);
    reduce_parts_kernel<<<(NSLOT * VB + 255) / 256, 256>>>(1, NSLOT * VB, 4);
    // z = h @ Wu1^T  -> gate
    wmma_gemm_kernel<2><<<dim3(32, 8, 1), 256>>>(2, HID, HID);
    gate_from_z_kernel<<<T_TOK / 8, 256>>>(bu1, Wu2, bu2, gate_w1, gate_b);
    // routing + slot attention + bottleneck-down (via AV2)
    router_kernel<<<T_TOK / 4, 256>>>(Wr, log_rel, aux_keys);
    // z2 = tmp @ Wvu^T ; out = h + gate*z2
    wmma_gemm_kernel<2><<<dim3(32, 32, 1), 256>>>(3, VB, VB);
    residual_kernel<<<T_TOK * HID / 4 / 256, 256>>>(H, out);
}

// round 6
// speedup vs baseline: 2.2791x; 1.1008x over previous
#include <cuda_runtime.h>
#include <cuda_bf16.h>
#include <cuda_pipeline.h>
#include <mma.h>
#include <math.h>

using namespace nvcuda;

// Problem constants
#define T_TOK 4096      // B*S
#define HID   4096
#define BOT   64
#define RDIM  48
#define NSLOT 1024
#define TOPK  8
#define VB    256
#define HID4  1024      // HID/4

typedef __nv_bfloat16 bf16;

// ---------------- scratch (static device memory; no allocations) ----------------
__device__ bf16  g_hb[(size_t)T_TOK * HID];      // bf16 copy of hidden_states
__device__ bf16  g_wu1b[HID4 * HID];
__device__ bf16  g_wqb[BOT * HID];
__device__ bf16  g_wvdb[VB * HID];
__device__ bf16  g_avb[NSLOT * HID];
__device__ bf16  g_wvub[HID * VB];
__device__ bf16  g_tmpb[T_TOK * VB];             // router output (bf16)
__device__ float g_zbuf[(size_t)T_TOK * HID4];   // h @ Wu1^T
__device__ float g_rkT[RDIM * NSLOT];            // rk transposed [48][1024]
__device__ float g_qpart[8 * T_TOK * BOT];
__device__ float g_query[T_TOK * BOT];
__device__ float g_AV2part[4 * NSLOT * VB];
__device__ float g_AV2[NSLOT * VB];              // aux_values @ Wvd^T
__device__ float g_logvar[T_TOK];
__device__ float g_mean[1];
__device__ float g_gate[T_TOK];

__device__ __forceinline__ float gelu_tanh(float x) {
    float x3 = x * x * x;
    return 0.5f * x * (1.0f + tanhf(0.7978845608028654f * (x + 0.044715f * x3)));
}

// ---------------- prepass: h -> bf16, fused per-token variance ----------------
__global__ __launch_bounds__(256) void conv_h_var_kernel(const float* __restrict__ H) {
    int row = blockIdx.x;
    int tid = threadIdx.x;
    const float4* h4 = (const float4*)(H + (size_t)row * HID);
    __nv_bfloat162* dst = (__nv_bfloat162*)(g_hb + (size_t)row * HID);
    float s = 0.f, sq = 0.f;
    for (int i = tid; i < HID / 4; i += 256) {
        float4 v = h4[i];
        s  += v.x + v.y + v.z + v.w;
        sq += v.x * v.x + v.y * v.y + v.z * v.z + v.w * v.w;
        dst[i * 2]     = __float22bfloat162_rn(make_float2(v.x, v.y));
        dst[i * 2 + 1] = __float22bfloat162_rn(make_float2(v.z, v.w));
    }
    __shared__ float ss[8], sqs[8];
#pragma unroll
    for (int o = 16; o; o >>= 1) {
        s  += __shfl_xor_sync(0xffffffffu, s, o);
        sq += __shfl_xor_sync(0xffffffffu, sq, o);
    }
    int w = tid >> 5, lane = tid & 31;
    if (lane == 0) { ss[w] = s; sqs[w] = sq; }
    __syncthreads();
    if (tid == 0) {
        float S = 0.f, SQ = 0.f;
#pragma unroll
        for (int i = 0; i < 8; i++) { S += ss[i]; SQ += sqs[i]; }
        float mean = S * (1.0f / HID);
        float var = SQ * (1.0f / HID) - mean * mean;
        g_logvar[row] = log1pf(var);
    }
}

__global__ void mean_kernel() {
    __shared__ float sm[1024];
    int tid = threadIdx.x;
    float s = g_logvar[tid] + g_logvar[tid + 1024] + g_logvar[tid + 2048] + g_logvar[tid + 3072];
    sm[tid] = s;
    __syncthreads();
    for (int o = 512; o; o >>= 1) {
        if (tid < o) sm[tid] += sm[tid + o];
        __syncthreads();
    }
    if (tid == 0) g_mean[0] = sm[0] * (1.0f / T_TOK);
}

// ---------------- all weight conversions in one kernel (range-partitioned grid) ------
#define CVT_N0 131072                 // Wq:  BOT*HID/2
#define CVT_N1 (CVT_N0 + 524288)      // Wvd: VB*HID/2
#define CVT_N2 (CVT_N1 + 2097152)     // av:  NSLOT*HID/2
#define CVT_N3 (CVT_N2 + 2097152)     // Wu1: HID4*HID/2
#define CVT_N4 (CVT_N3 + 524288)      // Wvu: HID*VB/2
__global__ void convert_all_kernel(const float* __restrict__ Wq, const float* __restrict__ Wvd,
                                   const float* __restrict__ av, const float* __restrict__ Wu1,
                                   const float* __restrict__ Wvu) {
    int i = blockIdx.x * 256 + threadIdx.x;
    const float* src; bf16* dst; int off;
    if (i < CVT_N0)      { src = Wq;  dst = g_wqb;  off = i; }
    else if (i < CVT_N1) { src = Wvd; dst = g_wvdb; off = i - CVT_N0; }
    else if (i < CVT_N2) { src = av;  dst = g_avb;  off = i - CVT_N1; }
    else if (i < CVT_N3) { src = Wu1; dst = g_wu1b; off = i - CVT_N2; }
    else if (i < CVT_N4) { src = Wvu; dst = g_wvub; off = i - CVT_N3; }
    else return;
    ((__nv_bfloat162*)dst)[off] = __float22bfloat162_rn(((const float2*)src)[off]);
}

// ---------------- tiny: rk^T = (aux_keys @ Wr^T)^T ----------------
__global__ void rk_kernel(const float* __restrict__ aux_keys,
                          const float* __restrict__ Wr) {
    int n = blockIdx.x * blockDim.x + threadIdx.x;
    if (n >= NSLOT) return;
    float ak[BOT];
#pragma unroll
    for (int d = 0; d < BOT; d++) ak[d] = aux_keys[n * BOT + d];
    for (int r = 0; r < RDIM; r++) {
        float s = 0.f;
#pragma unroll
        for (int d = 0; d < BOT; d++) s += ak[d] * Wr[r * BOT + d];
        g_rkT[r * NSLOT + n] = s;
    }
}

// ---------------- WMMA GEMM: C = A[M,K]bf16 @ B[N,K]bf16^T, 2-stage cp.async pipe ------
// Block tile 128 x (64*NF), BK=32, 8 warps (warp tile 64 x 16*NF).
// sel: 0 query (g_hb,g_wqb -> g_qpart)   1 AV2 (g_avb,g_wvdb -> g_AV2part)
//      2 g2    (g_hb,g_wu1b -> g_zbuf)   3 out (g_tmpb,g_wvub -> fused h + gate*z -> outp)
template<int NF>
__global__ __launch_bounds__(256) void wmma_gemm_kernel(int sel, int K, int kchunk,
                                                        const float* __restrict__ Hp,
                                                        float* __restrict__ outp) {
    constexpr int BN = 64 * NF;
    constexpr int WN = 16 * NF;
    const bf16* A; const bf16* B; float* C;
    if (sel == 0)      { A = g_hb;   B = g_wqb;  C = g_qpart;   }
    else if (sel == 1) { A = g_avb;  B = g_wvdb; C = g_AV2part; }
    else if (sel == 2) { A = g_hb;   B = g_wu1b; C = g_zbuf;    }
    else               { A = g_tmpb; B = g_wvub; C = nullptr;   }

    __shared__ bf16 As[2][128][40];
    __shared__ bf16 Bs[2][BN][40];
    int tid = threadIdx.x;
    int wid = tid >> 5;
    int warp_m = wid >> 2, warp_n = wid & 3;
    int m0 = blockIdx.x * 128, n0 = blockIdx.y * BN;
    int k0 = blockIdx.z * kchunk;
    int ldc = gridDim.y * BN;
    int M = gridDim.x * 128;

    wmma::fragment<wmma::accumulator, 16, 16, 16, float> c[4][NF];
#pragma unroll
    for (int i = 0; i < 4; i++)
#pragma unroll
        for (int j = 0; j < NF; j++) wmma::fill_fragment(c[i][j], 0.f);

    const int T = kchunk / 32;
    // async load of tile t into stage buf
    auto load_tile = [&](int t, int buf) {
        int kb = k0 + t * 32;
#pragma unroll
        for (int ch = tid; ch < 512; ch += 256) {
            int r = ch >> 2, cc = ch & 3;
            __pipeline_memcpy_async(&As[buf][r][cc * 8],
                                    A + (size_t)(m0 + r) * K + kb + cc * 8, 16);
        }
#pragma unroll
        for (int ch = tid; ch < BN * 4; ch += 256) {
            int r = ch >> 2, cc = ch & 3;
            __pipeline_memcpy_async(&Bs[buf][r][cc * 8],
                                    B + (size_t)(n0 + r) * K + kb + cc * 8, 16);
        }
        __pipeline_commit();
    };

    load_tile(0, 0);
    for (int t = 0; t < T; t++) {
        int buf = t & 1;
        if (t + 1 < T) {
            load_tile(t + 1, buf ^ 1);
            __pipeline_wait_prior(1);
        } else {
            __pipeline_wait_prior(0);
        }
        __syncthreads();
#pragma unroll
        for (int kk = 0; kk < 32; kk += 16) {
            wmma::fragment<wmma::matrix_a, 16, 16, 16, bf16, wmma::row_major> a[4];
            wmma::fragment<wmma::matrix_b, 16, 16, 16, bf16, wmma::col_major> b[NF];
#pragma unroll
            for (int i = 0; i < 4; i++)
                wmma::load_matrix_sync(a[i], &As[buf][warp_m * 64 + i * 16][kk], 40);
#pragma unroll
            for (int j = 0; j < NF; j++)
                wmma::load_matrix_sync(b[j], &Bs[buf][warp_n * WN + j * 16][kk], 40);
#pragma unroll
            for (int i = 0; i < 4; i++)
#pragma unroll
                for (int j = 0; j < NF; j++)
                    wmma::mma_sync(c[i][j], a[i], b[j], c[i][j]);
        }
        __syncthreads();
    }

    if (sel == 3) {
        // fused epilogue: out = h + gate * acc  (warp-private smem staging; NF==2 here)
        float* st = ((float*)As) + wid * 512;   // 16x32 floats per warp
        int lane = tid & 31;
#pragma unroll
        for (int i = 0; i < 4; i++) {
            wmma::store_matrix_sync(st, c[i][0], 32, wmma::mem_row_major);
            wmma::store_matrix_sync(st + 16, c[i][1], 32, wmma::mem_row_major);
            __syncwarp();
            int r = lane >> 1;
            int cb = (lane & 1) * 16;
            int grow = m0 + warp_m * 64 + i * 16 + r;
            int gcol = n0 + warp_n * 32 + cb;
            float g = g_gate[grow];
            const float4* h4 = (const float4*)(Hp + (size_t)grow * HID + gcol);
            float4* o4 = (float4*)(outp + (size_t)grow * HID + gcol);
#pragma unroll
            for (int v = 0; v < 4; v++) {
                float4 z = *(float4*)&st[r * 32 + cb + v * 4];
                float4 h = h4[v];
                o4[v] = make_float4(h.x + g * z.x, h.y + g * z.y,
                                    h.z + g * z.z, h.w + g * z.w);
            }
            __syncwarp();
        }
    } else {
        float* Cz = C + (size_t)blockIdx.z * M * ldc;
#pragma unroll
        for (int i = 0; i < 4; i++)
#pragma unroll
            for (int j = 0; j < NF; j++)
                wmma::store_matrix_sync(
                    &Cz[(size_t)(m0 + warp_m * 64 + i * 16) * ldc + n0 + warp_n * WN + j * 16],
                    c[i][j], ldc, wmma::mem_row_major);
    }
}

// which: 0 -> sum g_qpart into g_query, 1 -> sum g_AV2part into g_AV2
__global__ void reduce_parts_kernel(int which, int count, int z) {
    int i = blockIdx.x * blockDim.x + threadIdx.x;
    if (i >= count) return;
    const float* part = which ? g_AV2part : g_qpart;
    float s = 0.f;
    for (int p = 0; p < z; p++) s += part[(size_t)p * count + i];
    (which ? g_AV2 : g_query)[i] = s;
}

// ---------------- fused: learned = gelu(z+bu1)·Wu2, then gate ----------------
__global__ __launch_bounds__(256) void gate_from_z_kernel(
    const float* __restrict__ bu1, const float* __restrict__ Wu2,
    const float* __restrict__ bu2, const float* __restrict__ gw1,
    const float* __restrict__ gb) {
    int wid = threadIdx.x >> 5, lane = threadIdx.x & 31;
    int row = blockIdx.x * 8 + wid;
    const float4* z4 = (const float4*)(g_zbuf + (size_t)row * HID4);
    const float4* b4 = (const float4*)bu1;
    const float4* w4 = (const float4*)Wu2;
    float s = 0.f;
    for (int i = lane; i < HID4 / 4; i += 32) {
        float4 z = z4[i], b = b4[i], w = w4[i];
        s += gelu_tanh(z.x + b.x) * w.x + gelu_tanh(z.y + b.y) * w.y
           + gelu_tanh(z.z + b.z) * w.z + gelu_tanh(z.w + b.w) * w.w;
    }
#pragma unroll
    for (int o = 16; o; o >>= 1) s += __shfl_xor_sync(0xffffffffu, s, o);
    if (lane == 0) {
        float learned = s + bu2[0];
        float sl = 1.0f / (1.0f + expf(-learned));
        float nv = g_logvar[row] / (g_mean[0] + 1e-6f);
        float u = fminf(fmaxf(nv * 0.5f + sl * 2.5f, 0.0f), 5.0f);
        float un = fminf(fmaxf((u - 0.5f) * (1.0f / 1.5f), 0.0f), 1.0f);
        float g = 1.0f / (1.0f + expf(-(gw1[0] * un + gb[0])));
        if (g < 0.05f) g = 0.0f;
        g_gate[row] = g;
    }
}

// ---------------- router: scores, top-8, attn softmax, tmp = Σ w_k AV2[idx_k] ------
__global__ __launch_bounds__(256) void router_kernel(
    const float* __restrict__ Wr,       // [48,64]
    const float* __restrict__ log_rel,  // [1024]
    const float* __restrict__ aux_keys) // [1024,64]
{
    __shared__ float q[4][BOT];
    __shared__ float rq[4][RDIM];
    __shared__ float sc[4][NSLOT];
    __shared__ float redv[256];
    __shared__ int redi[256];
    __shared__ int sidx[4][TOPK];
    __shared__ float sw[4][TOPK];
    int tid = threadIdx.x;
    int tok0 = blockIdx.x * 4;

    q[tid >> 6][tid & 63] = g_query[(size_t)(tok0 + (tid >> 6)) * BOT + (tid & 63)];
    __syncthreads();
    if (tid < 4 * RDIM) {
        int tk = tid / RDIM, r = tid % RDIM;
        float s = 0.f;
#pragma unroll
        for (int d = 0; d < BOT; d++) s += q[tk][d] * Wr[r * BOT + d];
        rq[tk][r] = s;
    }
    __syncthreads();
    const float scale = 0.14433756729740643f; // 1/sqrt(48)
    for (int n = tid; n < NSLOT; n += 256) {
        float s0 = 0.f, s1 = 0.f, s2 = 0.f, s3 = 0.f;
#pragma unroll 8
        for (int r = 0; r < RDIM; r++) {
            float v = g_rkT[r * NSLOT + n];
            s0 += rq[0][r] * v; s1 += rq[1][r] * v;
            s2 += rq[2][r] * v; s3 += rq[3][r] * v;
        }
        float lr = log_rel[n];
        sc[0][n] = s0 * scale + lr; sc[1][n] = s1 * scale + lr;
        sc[2][n] = s2 * scale + lr; sc[3][n] = s3 * scale + lr;
    }
    __syncthreads();
    for (int tk = 0; tk < 4; tk++) {
        for (int it = 0; it < TOPK; it++) {
            float best = -3.0e38f; int bi = 1 << 30;
            for (int n = tid; n < NSLOT; n += 256) {
                float v = sc[tk][n];
                if (v > best || (v == best && n < bi)) { best = v; bi = n; }
            }
            redv[tid] = best; redi[tid] = bi;
            __syncthreads();
            for (int o = 128; o; o >>= 1) {
                if (tid < o) {
                    float v = redv[tid + o]; int i2 = redi[tid + o];
                    if (v > redv[tid] || (v == redv[tid] && i2 < redi[tid])) {
                        redv[tid] = v; redi[tid] = i2;
                    }
                }
                __syncthreads();
            }
            if (tid == 0) { sidx[tk][it] = redi[0]; sc[tk][redi[0]] = -3.0e38f; }
            __syncthreads();
        }
    }
    int w = tid >> 5, lane = tid & 31;
    for (int tk = 0; tk < 4; tk++) {
        int i = sidx[tk][w];
        float s = q[tk][lane] * aux_keys[i * BOT + lane] +
                  q[tk][lane + 32] * aux_keys[i * BOT + lane + 32];
#pragma unroll
        for (int o = 16; o; o >>= 1) s += __shfl_xor_sync(0xffffffffu, s, o);
        if (lane == 0) sw[tk][w] = s * 0.125f + log_rel[i];
    }
    __syncthreads();
    if (tid < 4) {
        int tk = tid;
        float m = -3.0e38f;
#pragma unroll
        for (int k2 = 0; k2 < TOPK; k2++) m = fmaxf(m, sw[tk][k2]);
        float e[TOPK], ssum = 0.f;
#pragma unroll
        for (int k2 = 0; k2 < TOPK; k2++) { e[k2] = expf(sw[tk][k2] - m); ssum += e[k2]; }
        float inv = 1.0f / ssum;
#pragma unroll
        for (int k2 = 0; k2 < TOPK; k2++) sw[tk][k2] = e[k2] * inv;
    }
    __syncthreads();
    for (int tk = 0; tk < 4; tk++) {
        float a = 0.f;
#pragma unroll
        for (int k2 = 0; k2 < TOPK; k2++)
            a += sw[tk][k2] * g_AV2[(size_t)sidx[tk][k2] * VB + tid];
        g_tmpb[(size_t)(tok0 + tk) * VB + tid] = __float2bfloat16(a);
    }
}

// ---------------- launch ----------------
extern "C" void kernel_launch(void* const* d_in, const int* in_sizes, int n_in,
                              void* d_out, int out_size) {
    const float* H        = (const float*)d_in[0];
    const float* Wq       = (const float*)d_in[1];
    const float* Wr       = (const float*)d_in[2];
    const float* aux_keys = (const float*)d_in[3];
    const float* aux_vals = (const float*)d_in[4];
    const float* Wvd      = (const float*)d_in[5];
    const float* Wvu      = (const float*)d_in[6];
    const float* Wu1      = (const float*)d_in[7];
    const float* bu1      = (const float*)d_in[8];
    const float* Wu2      = (const float*)d_in[9];
    const float* bu2      = (const float*)d_in[10];
    const float* gate_w1  = (const float*)d_in[11];
    const float* gate_b   = (const float*)d_in[12];
    const float* log_rel  = (const float*)d_in[13];
    float* out = (float*)d_out;

    // prepass
    conv_h_var_kernel<<<T_TOK, 256>>>(H);                                  // 1
    mean_kernel<<<1, 1024>>>();                                            // 2
    convert_all_kernel<<<(CVT_N4 + 255) / 256, 256>>>(Wq, Wvd, aux_vals, Wu1, Wvu); // 3
    rk_kernel<<<4, 256>>>(aux_keys, Wr);                                   // 4
    // query = h @ Wq^T  (k-split 8)
    wmma_gemm_kernel<1><<<dim3(32, 1, 8), 256>>>(0, HID, 512, nullptr, nullptr);    // 5
    // z = h @ Wu1^T
    wmma_gemm_kernel<2><<<dim3(32, 8, 1), 256>>>(2, HID, HID, nullptr, nullptr);    // 6
    reduce_parts_kernel<<<(T_TOK * BOT + 255) / 256, 256>>>(0, T_TOK * BOT, 8);
    // AV2 = aux_values @ Wvd^T  (k-split 4)
    wmma_gemm_kernel<2><<<dim3(8, 2, 4), 256>>>(1, HID, 1024, nullptr, nullptr);
    reduce_parts_kernel<<<(NSLOT * VB + 255) / 256, 256>>>(1, NSLOT * VB, 4);
    // gate
    gate_from_z_kernel<<<T_TOK / 8, 256>>>(bu1, Wu2, bu2, gate_w1, gate_b);
    // routing + slot attention + bottleneck-down (via AV2)
    router_kernel<<<T_TOK / 4, 256>>>(Wr, log_rel, aux_keys);
    // out = h + gate * (tmp @ Wvu^T)  (fused epilogue)
    wmma_gemm_kernel<2><<<dim3(32, 32, 1), 256>>>(3, VB, VB, H, out);
}